// round 14
// baseline (speedup 1.0000x reference)
#include <cuda_runtime.h>

#define NQ  512
#define NKV 512
#define DD  64
#define QT  8

typedef unsigned long long ull;

// proj scratch [b][k][c][e]; pad covers depth-2 prefetch overrun past k=511
// (up to 16 rows * 192 floats = 12 KB < 32 KB pad)
__device__ __align__(256) float g_proj[4 * NKV * 3 * DD + 8192];

// ---- packed fp32x2 math (per-lane IEEE fp32, identical rounding to scalar) ----
#define PACK2(d, lo, hi)   asm("mov.b64 %0, {%1, %2};" : "=l"(d) : "f"(lo), "f"(hi))
#define UNPACK2(lo, hi, s) asm("mov.b64 {%0, %1}, %2;" : "=f"(lo), "=f"(hi) : "l"(s))
#define FMA2(d, a, b, c)   asm("fma.rn.f32x2 %0, %1, %2, %3;" : "=l"(d) : "l"(a), "l"(b), "l"(c))
#define ADD2(d, a, b)      asm("add.rn.f32x2 %0, %1, %2;" : "=l"(d) : "l"(a), "l"(b))
#define MUL2(d, a, b)      asm("mul.rn.f32x2 %0, %1, %2;" : "=l"(d) : "l"(a), "l"(b))
// e = ex2(m * log2e) with the exact log2e constant __expf lowers to
#define EX2(d, a)          asm("ex2.approx.f32 %0, %1;" : "=f"(d) : "f"(a))

#define LDG2U64(lo, hi, ptr)                                            \
    asm("ld.global.nc.v2.u64 {%0,%1}, [%2];" : "=l"(lo), "=l"(hi) : "l"(ptr))

// Masked 16B stage fill: edge present -> async copy from DRAM; edge absent ->
// store {-inf x4} to the slot (NO DRAM request). Disjoint predicates = one
// writer per slot per stage, no race. Consume side then needs no mask test:
// ex2(-inf * log2e) = +0 exactly, matching the reference fp32 underflow of
// exp(-1e10 - max) for masked entries.
#define CPA16M(saddr, gptr, flag, ninf2)                                \
    asm volatile("{\n\t.reg .pred p;\n\t"                               \
                 "setp.ne.u32 p, %2, 0;\n\t"                            \
                 "@p cp.async.cg.shared.global [%0], [%1], 16;\n\t"     \
                 "@!p st.shared.v2.u64 [%0], {%3, %3};\n\t}"            \
                 :: "r"(saddr), "l"(gptr), "r"(flag), "l"(ninf2) : "memory")
#define CPCOMMIT() asm volatile("cp.async.commit_group;" ::: "memory")
#define CPWAIT3()  asm volatile("cp.async.wait_group 3;" ::: "memory")
#define CPWAIT0()  asm volatile("cp.async.wait_group 0;" ::: "memory")

#define LDSV2(v0, v1, saddr)                                            \
    asm("ld.shared.v2.u64 {%0,%1}, [%2];" : "=l"(v0), "=l"(v1) : "r"(saddr))

// ---------------------------------------------------------------------------
// Kernel A: proj[b,k,c,e] = sum_d v_equi[b,k,c,d] * w_coord[e,d]
// ---------------------------------------------------------------------------
__global__ __launch_bounds__(192) void proj_kernel(const float* __restrict__ v,
                                                   const float* __restrict__ w)
{
    __shared__ float ws[DD][68];
    __shared__ float vs[8 * 3 * DD];

    const int tid = threadIdx.x;
    const float4* w4 = (const float4*)w;
    for (int i = tid; i < DD * DD / 4; i += 192) {
        float4 t = w4[i];
        int e = i >> 4, d = (i & 15) * 4;
        *(float4*)&ws[e][d] = t;
    }
    const int bk0 = blockIdx.x * 8;
    const float4* v4 = (const float4*)(v + (size_t)bk0 * 3 * DD);
    for (int i = tid; i < 8 * 3 * DD / 4; i += 192)
        ((float4*)vs)[i] = v4[i];
    __syncthreads();

    const int c = tid / DD, e = tid % DD;
    float acc[8];
    #pragma unroll
    for (int kk = 0; kk < 8; ++kk) acc[kk] = 0.f;

    #pragma unroll 4
    for (int d4 = 0; d4 < 16; ++d4) {
        const float4 wv = *(const float4*)&ws[e][d4 * 4];
        #pragma unroll
        for (int kk = 0; kk < 8; ++kk) {
            const float4 vv = *(const float4*)&vs[(kk * 3 + c) * DD + d4 * 4];
            acc[kk] += vv.x * wv.x + vv.y * wv.y + vv.z * wv.z + vv.w * wv.w;
        }
    }
    #pragma unroll
    for (int kk = 0; kk < 8; ++kk)
        g_proj[(size_t)(bk0 + kk) * (3 * DD) + c * DD + e] = acc[kk];
}

// ---------------------------------------------------------------------------
// Kernel B: fused masked-softmax attention + L2-norm weighting + w_attn proj.
// Block = (b, 8 q's); grid = 256 -> single wave at 2 CTAs/SM.
// y = k-slice (k = y + 8*stage). q's in PAIRS: lanes 0-15 = even q (channels
// 4m..4m+3), lanes 16-31 = odd q. Messages flow through a per-warp depth-4
// cp.async.cg ring; masked stages are filled with -inf at PREFETCH time so
// the consume path is mask-free and fully packed (MUL2 -> ex2 -> FMA2).
// Proj rows ride a depth-2 register pipeline (~2 stages of L2-latency cover).
// ---------------------------------------------------------------------------
__global__ __launch_bounds__(256, 2) void attn_kernel(
    const float* __restrict__ messages,
    const int*   __restrict__ adj,
    const float* __restrict__ w_attn,
    float*       __restrict__ out)
{
    extern __shared__ char dsm[];              // 64 KB ring; aliased epilogue

    const int x    = threadIdx.x;
    const int y    = threadIdx.y;
    const int tid  = y * 32 + x;
    const int b    = blockIdx.x >> 6;          // NQ/QT = 64 q-tiles per batch
    const int q0   = (blockIdx.x & 63) * QT;
    const int half = x >> 4;                   // 0: even q of pair, 1: odd q
    const int m    = x & 15;                   // channel group 4m..4m+3

    // ring layout: [y][slot 0..3][pair 0..3][lane 0..31] * 16 B
    const unsigned rbase =
        (unsigned)__cvta_generic_to_shared(dsm) + y * 8192 + x * 16;

    // Masks as 64-bit shift registers per PAIR (lane-selected even/odd q).
    // bit i of (mhi:mlo) = adj(q_pair, k = y + 8i) = stage i. Prefetch-only.
    unsigned mlo[4], mhi[4];
    {
        const int* adjb = adj + ((size_t)b * NQ + q0) * NKV;
        #pragma unroll
        for (int j = 0; j < 4; ++j) {
            unsigned le = __ballot_sync(~0u, adjb[(2 * j) * NKV + y + 8 * x] > 0);
            unsigned lo = __ballot_sync(~0u, adjb[(2 * j + 1) * NKV + y + 8 * x] > 0);
            unsigned he = __ballot_sync(~0u, adjb[(2 * j) * NKV + y + 256 + 8 * x] > 0);
            unsigned ho = __ballot_sync(~0u, adjb[(2 * j + 1) * NKV + y + 256 + 8 * x] > 0);
            mlo[j] = (x < 16) ? le : lo;
            mhi[j] = (x < 16) ? he : ho;
        }
    }

    // Accumulators A[pair][kind][chan-half]; kind 0:s 1:s2 2..4:a0..a2
    ull A[4][5][2];
    #pragma unroll
    for (int j = 0; j < 4; ++j)
        #pragma unroll
        for (int kk = 0; kk < 5; ++kk) { A[j][kk][0] = 0ull; A[j][kk][1] = 0ull; }

    const ull NINF2 = 0xFF800000FF800000ull;
    ull L2E2;
    {
        const float L2EF = __uint_as_float(0x3FB8AA3Bu);
        PACK2(L2E2, L2EF, L2EF);
    }

    // msg byte cursor: element ((b*NQ+q0+2j+half)*NKV + y+8s)*64 + 4m floats.
    // q-pair j offset = j * 2*NKV*DD*4 = j * 262144 bytes.
    const char* msrc = (const char*)messages
                     + (((size_t)(b * NQ + q0 + half) * NKV + y) * DD + 4 * m) * 4;
    // proj byte cursor: element ((b*NKV + k)*3 + c)*64 + 4m floats
    const char* ppc = (const char*)g_proj
                    + (((size_t)b * NKV + y) * 192 + 4 * m) * 4;

    // proj depth-2: pj[0] = stage s (even), pj[1] = stage s+1 (odd);
    // ppc points at stage s+2.
    ull pj[2][3][2];
    LDG2U64(pj[0][0][0], pj[0][0][1], ppc);
    LDG2U64(pj[0][1][0], pj[0][1][1], ppc + 256);
    LDG2U64(pj[0][2][0], pj[0][2][1], ppc + 512);
    LDG2U64(pj[1][0][0], pj[1][0][1], ppc + 6144);
    LDG2U64(pj[1][1][0], pj[1][1][1], ppc + 6144 + 256);
    LDG2U64(pj[1][2][0], pj[1][2][1], ppc + 6144 + 512);
    ppc += 2 * 6144;

    // ---- prime ring stages 0..2 into slots 0..2 ----
    #pragma unroll
    for (int st = 0; st < 3; ++st) {
        #pragma unroll
        for (int j = 0; j < 4; ++j)
            CPA16M(rbase + st * 2048 + j * 512,
                   msrc + st * 2048 + j * 262144,
                   mlo[j] & (1u << st), NINF2);
        CPCOMMIT();
    }

    const char* psrc = msrc + 3 * 2048;        // prefetch cursor: stage s+3

    #pragma unroll 1
    for (int o = 0; o < 16; ++o) {
        #pragma unroll
        for (int t = 0; t < 4; ++t) {
            // prefetch stage 4o+t+3 into slot (t+3)&3
            #pragma unroll
            for (int j = 0; j < 4; ++j)
                CPA16M(rbase + (((t + 3) & 3) * 2048) + j * 512,
                       psrc + j * 262144,
                       mlo[j] & (8u << t), NINF2);
            psrc += 2048;
            CPCOMMIT();
            CPWAIT3();                          // stage 4o+t resident

            // mask-free packed consume of stage 4o+t
            #pragma unroll
            for (int j = 0; j < 4; ++j) {
                ull v0, v1;
                LDSV2(v0, v1, rbase + t * 2048 + j * 512);
                ull w0, w1;
                MUL2(w0, v0, L2E2); MUL2(w1, v1, L2E2);
                float f0, f1, f2, f3;
                UNPACK2(f0, f1, w0); UNPACK2(f2, f3, w1);
                float e0, e1, e2, e3;
                EX2(e0, f0); EX2(e1, f1); EX2(e2, f2); EX2(e3, f3);
                ull ev0, ev1;
                PACK2(ev0, e0, e1); PACK2(ev1, e2, e3);
                ADD2(A[j][0][0], A[j][0][0], ev0);  ADD2(A[j][0][1], A[j][0][1], ev1);
                FMA2(A[j][1][0], ev0, ev0, A[j][1][0]);
                FMA2(A[j][1][1], ev1, ev1, A[j][1][1]);
                FMA2(A[j][2][0], ev0, pj[t & 1][0][0], A[j][2][0]);
                FMA2(A[j][2][1], ev1, pj[t & 1][0][1], A[j][2][1]);
                FMA2(A[j][3][0], ev0, pj[t & 1][1][0], A[j][3][0]);
                FMA2(A[j][3][1], ev1, pj[t & 1][1][1], A[j][3][1]);
                FMA2(A[j][4][0], ev0, pj[t & 1][2][0], A[j][4][0]);
                FMA2(A[j][4][1], ev1, pj[t & 1][2][1], A[j][4][1]);
            }
            // proj refill: stage 4o+t+2 into the set just consumed
            // (used 2 stages from now -> ~2 stages of latency cover)
            LDG2U64(pj[t & 1][0][0], pj[t & 1][0][1], ppc);
            LDG2U64(pj[t & 1][1][0], pj[t & 1][1][1], ppc + 256);
            LDG2U64(pj[t & 1][2][0], pj[t & 1][2][1], ppc + 512);
            ppc += 6144;
        }
        #pragma unroll
        for (int j = 0; j < 4; ++j) {
            mlo[j] = __funnelshift_r(mlo[j], mhi[j], 4);
            mhi[j] >>= 4;
        }
    }

    CPWAIT0();                                  // ring fully drained
    __syncthreads();                            // before aliased epilogue smem

    // ---- aliased epilogue layout over the (dead) ring ----
    float* wat = (float*)dsm;                                  // 16640 B
    ull (*redu)[32][5][2] = (ull (*)[32][5][2])(dsm + 16640);  // 20480 B
    float (*pre)[3][DD]   = (float (*)[3][DD])(dsm + 37120);   // 6144 B

    // w_attn -> smem transposed, pad 65
    for (int i = tid; i < DD * DD; i += 256) {
        int e = i >> 6, d = i & 63;
        wat[d * 65 + e] = w_attn[i];
    }

    // Stage 3: reduce 8 k-slices, one PAIR (2 q's) per pass; fold weights:
    // pre[c][d] = acc_c * sqrt(s2) / s^2
    #pragma unroll 1
    for (int j = 0; j < 4; ++j) {
        __syncthreads();
        #pragma unroll
        for (int kk = 0; kk < 5; ++kk) {
            redu[y][x][kk][0] = A[j][kk][0];
            redu[y][x][kk][1] = A[j][kk][1];
        }
        __syncthreads();
        if (tid < 64) {
            const int dlt = tid >> 5;          // which q of the pair
            const int xx  = tid & 31;          // channel pair 2xx, 2xx+1
            const int l   = dlt * 16 + (xx >> 1);
            const int hh  = xx & 1;
            ull S0 = redu[0][l][0][hh], S1 = redu[0][l][1][hh];
            ull S2 = redu[0][l][2][hh], S3 = redu[0][l][3][hh], S4 = redu[0][l][4][hh];
            #pragma unroll
            for (int yy = 1; yy < 8; ++yy) {
                ADD2(S0, S0, redu[yy][l][0][hh]);
                ADD2(S1, S1, redu[yy][l][1][hh]);
                ADD2(S2, S2, redu[yy][l][2][hh]);
                ADD2(S3, S3, redu[yy][l][3][hh]);
                ADD2(S4, S4, redu[yy][l][4][hh]);
            }
            float Sx, Sy, S2x, S2y, ax, ay;
            UNPACK2(Sx, Sy, S0);
            UNPACK2(S2x, S2y, S1);
            const float scx = sqrtf(S2x) / (Sx * Sx);
            const float scy = sqrtf(S2y) / (Sy * Sy);
            const int q = 2 * j + dlt;
            float2* pre2 = (float2*)pre;
            UNPACK2(ax, ay, S2); pre2[(q * 3 + 0) * 32 + xx] = make_float2(ax * scx, ay * scy);
            UNPACK2(ax, ay, S3); pre2[(q * 3 + 1) * 32 + xx] = make_float2(ax * scx, ay * scy);
            UNPACK2(ax, ay, S4); pre2[(q * 3 + 2) * 32 + xx] = make_float2(ax * scx, ay * scy);
        }
    }
    __syncthreads();

    // Stage 4: out[q,c,e] = sum_d pre[q,c,d] * w_attn[e,d]   (QT*3*64 = 1536)
    float* outb = out + (size_t)(b * NQ + q0) * (3 * DD);
    #pragma unroll
    for (int jj = 0; jj < 6; ++jj) {
        const int oid = tid + jj * 256;        // (q*3+c)*64 + e
        const int e  = oid & 63;
        const int cq = oid >> 6;
        const int c  = cq % 3, q = cq / 3;
        float acc = 0.f;
        #pragma unroll
        for (int d = 0; d < DD; ++d)
            acc += pre[q][c][d] * wat[d * 65 + e];
        outb[oid] = acc;
    }
}

// ---------------------------------------------------------------------------
extern "C" void kernel_launch(void* const* d_in, const int* in_sizes, int n_in,
                              void* d_out, int out_size)
{
    const float* v_equi   = (const float*)d_in[0];
    const float* messages = (const float*)d_in[1];
    const int*   adj      = (const int*)d_in[2];
    const float* w_coord  = (const float*)d_in[3];
    const float* w_attn   = (const float*)d_in[4];
    float* out = (float*)d_out;

    const int B = in_sizes[2] / (NQ * NKV);    // adj element count -> batch

    proj_kernel<<<B * NKV / 8, 192>>>(v_equi, w_coord);

    cudaFuncSetAttribute(attn_kernel,
                         cudaFuncAttributeMaxDynamicSharedMemorySize, 65536);
    dim3 blk(32, 8);
    attn_kernel<<<B * (NQ / QT), blk, 65536>>>(messages, adj, w_attn, out);
}

// round 15
// speedup vs baseline: 1.0233x; 1.0233x over previous
#include <cuda_runtime.h>

#define NQ  512
#define NKV 512
#define DD  64
#define QT  8

typedef unsigned long long ull;

// proj scratch [b][k][c][e]; pad covers depth-2 prefetch overrun past k=511
__device__ __align__(256) float g_proj[4 * NKV * 3 * DD + 8192];

// ---- packed fp32x2 math (per-lane IEEE fp32, identical rounding to scalar) ----
#define PACK2(d, lo, hi)   asm("mov.b64 %0, {%1, %2};" : "=l"(d) : "f"(lo), "f"(hi))
#define UNPACK2(lo, hi, s) asm("mov.b64 {%0, %1}, %2;" : "=f"(lo), "=f"(hi) : "l"(s))
#define FMA2(d, a, b, c)   asm("fma.rn.f32x2 %0, %1, %2, %3;" : "=l"(d) : "l"(a), "l"(b), "l"(c))
#define ADD2(d, a, b)      asm("add.rn.f32x2 %0, %1, %2;" : "=l"(d) : "l"(a), "l"(b))
#define MUL2(d, a, b)      asm("mul.rn.f32x2 %0, %1, %2;" : "=l"(d) : "l"(a), "l"(b))
#define EX2(d, a)          asm("ex2.approx.f32 %0, %1;" : "=f"(d) : "f"(a))

#define CPCOMMIT() asm volatile("cp.async.commit_group;" ::: "memory")
#define CPWAIT3()  asm volatile("cp.async.wait_group 3;" ::: "memory")
#define CPWAIT0()  asm volatile("cp.async.wait_group 0;" ::: "memory")

// Masked 16B stage fill with IMMEDIATE offsets (SOFF/GOFF must be integral
// constant expressions). Edge present -> cp.async from DRAM; edge absent ->
// st.shared {-inf x4} (NO DRAM request). Disjoint predicates = single writer
// per slot per stage. Consume side is mask-free: ex2(-inf*log2e) = +0
// exactly, matching the reference fp32 underflow of exp(-1e10 - max).
#define CPA16MI(sbase, SOFF, gbase, GOFF, flag, ninf2)                  \
    asm volatile("{\n\t.reg .pred p;\n\t"                               \
                 "setp.ne.u32 p, %2, 0;\n\t"                            \
                 "@p cp.async.cg.shared.global [%0+%3], [%1+%4], 16;\n\t" \
                 "@!p st.shared.v2.u64 [%0+%3], {%5, %5};\n\t}"         \
                 :: "r"(sbase), "l"(gbase), "r"(flag),                  \
                    "n"(SOFF), "n"(GOFF), "l"(ninf2) : "memory")

#define LDSV2I(v0, v1, sbase, SOFF)                                     \
    asm("ld.shared.v2.u64 {%0,%1}, [%2+%3];"                            \
        : "=l"(v0), "=l"(v1) : "r"(sbase), "n"(SOFF))

#define LDGPJI(lo, hi, gbase, GOFF)                                     \
    asm("ld.global.nc.v2.u64 {%0,%1}, [%2+%3];"                         \
        : "=l"(lo), "=l"(hi) : "l"(gbase), "n"(GOFF))

// ---------------------------------------------------------------------------
// Kernel A: proj[b,k,c,e] = sum_d v_equi[b,k,c,d] * w_coord[e,d]
// ---------------------------------------------------------------------------
__global__ __launch_bounds__(192) void proj_kernel(const float* __restrict__ v,
                                                   const float* __restrict__ w)
{
    __shared__ float ws[DD][68];
    __shared__ float vs[8 * 3 * DD];

    const int tid = threadIdx.x;
    const float4* w4 = (const float4*)w;
    for (int i = tid; i < DD * DD / 4; i += 192) {
        float4 t = w4[i];
        int e = i >> 4, d = (i & 15) * 4;
        *(float4*)&ws[e][d] = t;
    }
    const int bk0 = blockIdx.x * 8;
    const float4* v4 = (const float4*)(v + (size_t)bk0 * 3 * DD);
    for (int i = tid; i < 8 * 3 * DD / 4; i += 192)
        ((float4*)vs)[i] = v4[i];
    __syncthreads();

    const int c = tid / DD, e = tid % DD;
    float acc[8];
    #pragma unroll
    for (int kk = 0; kk < 8; ++kk) acc[kk] = 0.f;

    #pragma unroll 4
    for (int d4 = 0; d4 < 16; ++d4) {
        const float4 wv = *(const float4*)&ws[e][d4 * 4];
        #pragma unroll
        for (int kk = 0; kk < 8; ++kk) {
            const float4 vv = *(const float4*)&vs[(kk * 3 + c) * DD + d4 * 4];
            acc[kk] += vv.x * wv.x + vv.y * wv.y + vv.z * wv.z + vv.w * wv.w;
        }
    }
    #pragma unroll
    for (int kk = 0; kk < 8; ++kk)
        g_proj[(size_t)(bk0 + kk) * (3 * DD) + c * DD + e] = acc[kk];
}

// ---------------------------------------------------------------------------
// Kernel B: fused masked-softmax attention + L2-norm weighting + w_attn proj.
// Identical dataflow to round-13/14 (depth-4 per-warp cp.async ring, -inf
// prefetch fill, depth-2 proj register pipeline), but ALL hot-loop addresses
// are base-register + IMMEDIATE: the 4-stage group and 4 q-pairs are
// hand-unrolled via macros with literal T/J so every offset is a constant
// expression. Base pointers advance once per group.
// ---------------------------------------------------------------------------

// Consume one (stage T, pair J): mask-free packed exp + accumulate.
#define CONSUME(T, J)                                                   \
    do {                                                                \
        ull v0, v1;                                                     \
        LDSV2I(v0, v1, rbase, (T) * 2048 + (J) * 512);                  \
        ull w0, w1;                                                     \
        MUL2(w0, v0, L2E2); MUL2(w1, v1, L2E2);                         \
        float f0, f1, f2, f3;                                           \
        UNPACK2(f0, f1, w0); UNPACK2(f2, f3, w1);                       \
        float e0, e1, e2, e3;                                           \
        EX2(e0, f0); EX2(e1, f1); EX2(e2, f2); EX2(e3, f3);             \
        ull ev0, ev1;                                                   \
        PACK2(ev0, e0, e1); PACK2(ev1, e2, e3);                         \
        ADD2(A[J][0][0], A[J][0][0], ev0);                              \
        ADD2(A[J][0][1], A[J][0][1], ev1);                              \
        FMA2(A[J][1][0], ev0, ev0, A[J][1][0]);                         \
        FMA2(A[J][1][1], ev1, ev1, A[J][1][1]);                         \
        FMA2(A[J][2][0], ev0, pj[(T) & 1][0][0], A[J][2][0]);           \
        FMA2(A[J][2][1], ev1, pj[(T) & 1][0][1], A[J][2][1]);           \
        FMA2(A[J][3][0], ev0, pj[(T) & 1][1][0], A[J][3][0]);           \
        FMA2(A[J][3][1], ev1, pj[(T) & 1][1][1], A[J][3][1]);           \
        FMA2(A[J][4][0], ev0, pj[(T) & 1][2][0], A[J][4][0]);           \
        FMA2(A[J][4][1], ev1, pj[(T) & 1][2][1], A[J][4][1]);           \
    } while (0)

// One stage of the group: prefetch stage (4o+T+3), consume stage (4o+T),
// refill proj set (T&1) with stage (4o+T+2). mp4 = msrc of stage 4o+3;
// pp4 = proj of stage 4o+2.
#define STAGE(T)                                                        \
    do {                                                                \
        CPA16MI(rbase, (((T) + 3) & 3) * 2048 + 0 * 512,                \
                mp4, (T) * 2048 + 0 * 262144, mlo[0] & (8u << (T)), NINF2); \
        CPA16MI(rbase, (((T) + 3) & 3) * 2048 + 1 * 512,                \
                mp4, (T) * 2048 + 1 * 262144, mlo[1] & (8u << (T)), NINF2); \
        CPA16MI(rbase, (((T) + 3) & 3) * 2048 + 2 * 512,                \
                mp4, (T) * 2048 + 2 * 262144, mlo[2] & (8u << (T)), NINF2); \
        CPA16MI(rbase, (((T) + 3) & 3) * 2048 + 3 * 512,                \
                mp4, (T) * 2048 + 3 * 262144, mlo[3] & (8u << (T)), NINF2); \
        CPCOMMIT();                                                     \
        CPWAIT3();                                                      \
        CONSUME(T, 0); CONSUME(T, 1); CONSUME(T, 2); CONSUME(T, 3);     \
        LDGPJI(pj[(T) & 1][0][0], pj[(T) & 1][0][1], pp4, (T) * 6144 + 0);   \
        LDGPJI(pj[(T) & 1][1][0], pj[(T) & 1][1][1], pp4, (T) * 6144 + 256); \
        LDGPJI(pj[(T) & 1][2][0], pj[(T) & 1][2][1], pp4, (T) * 6144 + 512); \
    } while (0)

__global__ __launch_bounds__(256, 2) void attn_kernel(
    const float* __restrict__ messages,
    const int*   __restrict__ adj,
    const float* __restrict__ w_attn,
    float*       __restrict__ out)
{
    extern __shared__ char dsm[];              // 64 KB ring; aliased epilogue

    const int x    = threadIdx.x;
    const int y    = threadIdx.y;
    const int tid  = y * 32 + x;
    const int b    = blockIdx.x >> 6;          // NQ/QT = 64 q-tiles per batch
    const int q0   = (blockIdx.x & 63) * QT;
    const int half = x >> 4;                   // 0: even q of pair, 1: odd q
    const int m    = x & 15;                   // channel group 4m..4m+3

    // ring layout: [y][slot 0..3][pair 0..3][lane 0..31] * 16 B
    const unsigned rbase =
        (unsigned)__cvta_generic_to_shared(dsm) + y * 8192 + x * 16;

    // Masks as 64-bit shift registers per PAIR (lane-selected even/odd q).
    // bit i of (mhi:mlo) = adj(q_pair, k = y + 8i) = stage i. Prefetch-only.
    unsigned mlo[4], mhi[4];
    {
        const int* adjb = adj + ((size_t)b * NQ + q0) * NKV;
        #pragma unroll
        for (int j = 0; j < 4; ++j) {
            unsigned le = __ballot_sync(~0u, adjb[(2 * j) * NKV + y + 8 * x] > 0);
            unsigned lo = __ballot_sync(~0u, adjb[(2 * j + 1) * NKV + y + 8 * x] > 0);
            unsigned he = __ballot_sync(~0u, adjb[(2 * j) * NKV + y + 256 + 8 * x] > 0);
            unsigned ho = __ballot_sync(~0u, adjb[(2 * j + 1) * NKV + y + 256 + 8 * x] > 0);
            mlo[j] = (x < 16) ? le : lo;
            mhi[j] = (x < 16) ? he : ho;
        }
    }

    // Accumulators A[pair][kind][chan-half]; kind 0:s 1:s2 2..4:a0..a2
    ull A[4][5][2];
    #pragma unroll
    for (int j = 0; j < 4; ++j)
        #pragma unroll
        for (int kk = 0; kk < 5; ++kk) { A[j][kk][0] = 0ull; A[j][kk][1] = 0ull; }

    const ull NINF2 = 0xFF800000FF800000ull;
    ull L2E2;
    {
        const float L2EF = __uint_as_float(0x3FB8AA3Bu);
        PACK2(L2E2, L2EF, L2EF);
    }

    // msg byte cursor: element ((b*NQ+q0+2j+half)*NKV + y+8s)*64 + 4m floats
    const char* msrc = (const char*)messages
                     + (((size_t)(b * NQ + q0 + half) * NKV + y) * DD + 4 * m) * 4;
    // proj byte cursor: element ((b*NKV + k)*3 + c)*64 + 4m floats
    const char* ppc = (const char*)g_proj
                    + (((size_t)b * NKV + y) * 192 + 4 * m) * 4;

    // proj depth-2: pj[0]=even stage, pj[1]=odd stage; pp4 -> stage s+2
    ull pj[2][3][2];
    LDGPJI(pj[0][0][0], pj[0][0][1], ppc, 0);
    LDGPJI(pj[0][1][0], pj[0][1][1], ppc, 256);
    LDGPJI(pj[0][2][0], pj[0][2][1], ppc, 512);
    LDGPJI(pj[1][0][0], pj[1][0][1], ppc, 6144);
    LDGPJI(pj[1][1][0], pj[1][1][1], ppc, 6144 + 256);
    LDGPJI(pj[1][2][0], pj[1][2][1], ppc, 6144 + 512);

    // ---- prime ring stages 0..2 into slots 0..2 (all-immediate) ----
    CPA16MI(rbase, 0 * 2048 + 0 * 512, msrc, 0 * 2048 + 0 * 262144, mlo[0] & 1u, NINF2);
    CPA16MI(rbase, 0 * 2048 + 1 * 512, msrc, 0 * 2048 + 1 * 262144, mlo[1] & 1u, NINF2);
    CPA16MI(rbase, 0 * 2048 + 2 * 512, msrc, 0 * 2048 + 2 * 262144, mlo[2] & 1u, NINF2);
    CPA16MI(rbase, 0 * 2048 + 3 * 512, msrc, 0 * 2048 + 3 * 262144, mlo[3] & 1u, NINF2);
    CPCOMMIT();
    CPA16MI(rbase, 1 * 2048 + 0 * 512, msrc, 1 * 2048 + 0 * 262144, mlo[0] & 2u, NINF2);
    CPA16MI(rbase, 1 * 2048 + 1 * 512, msrc, 1 * 2048 + 1 * 262144, mlo[1] & 2u, NINF2);
    CPA16MI(rbase, 1 * 2048 + 2 * 512, msrc, 1 * 2048 + 2 * 262144, mlo[2] & 2u, NINF2);
    CPA16MI(rbase, 1 * 2048 + 3 * 512, msrc, 1 * 2048 + 3 * 262144, mlo[3] & 2u, NINF2);
    CPCOMMIT();
    CPA16MI(rbase, 2 * 2048 + 0 * 512, msrc, 2 * 2048 + 0 * 262144, mlo[0] & 4u, NINF2);
    CPA16MI(rbase, 2 * 2048 + 1 * 512, msrc, 2 * 2048 + 1 * 262144, mlo[1] & 4u, NINF2);
    CPA16MI(rbase, 2 * 2048 + 2 * 512, msrc, 2 * 2048 + 2 * 262144, mlo[2] & 4u, NINF2);
    CPA16MI(rbase, 2 * 2048 + 3 * 512, msrc, 2 * 2048 + 3 * 262144, mlo[3] & 4u, NINF2);
    CPCOMMIT();

    const char* mp4 = msrc + 3 * 2048;         // msg src of stage 4o+3
    const char* pp4 = ppc + 2 * 6144;          // proj of stage 4o+2

    #pragma unroll 1
    for (int o = 0; o < 16; ++o) {
        STAGE(0);
        STAGE(1);
        STAGE(2);
        STAGE(3);
        #pragma unroll
        for (int j = 0; j < 4; ++j) {
            mlo[j] = __funnelshift_r(mlo[j], mhi[j], 4);
            mhi[j] >>= 4;
        }
        mp4 += 4 * 2048;
        pp4 += 4 * 6144;
    }

    CPWAIT0();                                  // ring fully drained
    __syncthreads();                            // before aliased epilogue smem

    // ---- aliased epilogue layout over the (dead) ring ----
    float* wat = (float*)dsm;                                  // 16640 B
    ull (*redu)[32][5][2] = (ull (*)[32][5][2])(dsm + 16640);  // 20480 B
    float (*pre)[3][DD]   = (float (*)[3][DD])(dsm + 37120);   // 6144 B

    // w_attn -> smem transposed, pad 65
    for (int i = tid; i < DD * DD; i += 256) {
        int e = i >> 6, d = i & 63;
        wat[d * 65 + e] = w_attn[i];
    }

    // Stage 3: reduce 8 k-slices, one PAIR (2 q's) per pass; fold weights:
    // pre[c][d] = acc_c * sqrt(s2) / s^2
    #pragma unroll 1
    for (int j = 0; j < 4; ++j) {
        __syncthreads();
        #pragma unroll
        for (int kk = 0; kk < 5; ++kk) {
            redu[y][x][kk][0] = A[j][kk][0];
            redu[y][x][kk][1] = A[j][kk][1];
        }
        __syncthreads();
        if (tid < 64) {
            const int dlt = tid >> 5;          // which q of the pair
            const int xx  = tid & 31;          // channel pair 2xx, 2xx+1
            const int l   = dlt * 16 + (xx >> 1);
            const int hh  = xx & 1;
            ull S0 = redu[0][l][0][hh], S1 = redu[0][l][1][hh];
            ull S2 = redu[0][l][2][hh], S3 = redu[0][l][3][hh], S4 = redu[0][l][4][hh];
            #pragma unroll
            for (int yy = 1; yy < 8; ++yy) {
                ADD2(S0, S0, redu[yy][l][0][hh]);
                ADD2(S1, S1, redu[yy][l][1][hh]);
                ADD2(S2, S2, redu[yy][l][2][hh]);
                ADD2(S3, S3, redu[yy][l][3][hh]);
                ADD2(S4, S4, redu[yy][l][4][hh]);
            }
            float Sx, Sy, S2x, S2y, ax, ay;
            UNPACK2(Sx, Sy, S0);
            UNPACK2(S2x, S2y, S1);
            const float scx = sqrtf(S2x) / (Sx * Sx);
            const float scy = sqrtf(S2y) / (Sy * Sy);
            const int q = 2 * j + dlt;
            float2* pre2 = (float2*)pre;
            UNPACK2(ax, ay, S2); pre2[(q * 3 + 0) * 32 + xx] = make_float2(ax * scx, ay * scy);
            UNPACK2(ax, ay, S3); pre2[(q * 3 + 1) * 32 + xx] = make_float2(ax * scx, ay * scy);
            UNPACK2(ax, ay, S4); pre2[(q * 3 + 2) * 32 + xx] = make_float2(ax * scx, ay * scy);
        }
    }
    __syncthreads();

    // Stage 4: out[q,c,e] = sum_d pre[q,c,d] * w_attn[e,d]   (QT*3*64 = 1536)
    float* outb = out + (size_t)(b * NQ + q0) * (3 * DD);
    #pragma unroll
    for (int jj = 0; jj < 6; ++jj) {
        const int oid = tid + jj * 256;        // (q*3+c)*64 + e
        const int e  = oid & 63;
        const int cq = oid >> 6;
        const int c  = cq % 3, q = cq / 3;
        float acc = 0.f;
        #pragma unroll
        for (int d = 0; d < DD; ++d)
            acc += pre[q][c][d] * wat[d * 65 + e];
        outb[oid] = acc;
    }
}

// ---------------------------------------------------------------------------
extern "C" void kernel_launch(void* const* d_in, const int* in_sizes, int n_in,
                              void* d_out, int out_size)
{
    const float* v_equi   = (const float*)d_in[0];
    const float* messages = (const float*)d_in[1];
    const int*   adj      = (const int*)d_in[2];
    const float* w_coord  = (const float*)d_in[3];
    const float* w_attn   = (const float*)d_in[4];
    float* out = (float*)d_out;

    const int B = in_sizes[2] / (NQ * NKV);    // adj element count -> batch

    proj_kernel<<<B * NKV / 8, 192>>>(v_equi, w_coord);

    cudaFuncSetAttribute(attn_kernel,
                         cudaFuncAttributeMaxDynamicSharedMemorySize, 65536);
    dim3 blk(32, 8);
    attn_kernel<<<B * (NQ / QT), blk, 65536>>>(messages, adj, w_attn, out);
}